// round 3
// baseline (speedup 1.0000x reference)
#include <cuda_runtime.h>

#define BB 2048
#define SS 1024
#define FF 64
#define BI 64
#define BJ 64
#define KC 32
#define TI 4
#define TJ 4

// Precomputed half-angle sin/cos tables, f-major: [f][row]
__device__ float g_cX[FF * BB];
__device__ float g_sX[FF * BB];
__device__ float g_cS[FF * SS];
__device__ float g_sS[FF * SS];

__global__ void precomp_kernel(const float* __restrict__ X,
                               const float* __restrict__ Sp) {
    int n = blockIdx.x * blockDim.x + threadIdx.x;
    if (n < FF * BB) {
        int f = n / BB, i = n % BB;
        float s, c;
        sincosf(0.5f * X[i * FF + f], &s, &c);
        g_cX[n] = c;
        g_sX[n] = s;
    } else {
        int m = n - FF * BB;
        if (m < FF * SS) {
            int f = m / SS, j = m % SS;
            float s, c;
            sincosf(0.5f * Sp[j * FF + f], &s, &c);
            g_cS[m] = c;
            g_sS[m] = s;
        }
    }
}

__global__ void init_kernel(float* __restrict__ out, const float* __restrict__ b) {
    int i = blockIdx.x * blockDim.x + threadIdx.x;
    if (i < BB) out[i] = b[0];
}

__global__ __launch_bounds__(256, 2) void main_kernel(const float* __restrict__ W,
                                                      float* __restrict__ out) {
    __shared__ __align__(16) float sCX[KC][BI];
    __shared__ __align__(16) float sSX[KC][BI];
    __shared__ __align__(16) float sCS[KC][BJ];
    __shared__ __align__(16) float sSS[KC][BJ];
    __shared__ float sW[BJ];

    const int tid = threadIdx.x;
    const int tx = tid & 15;   // j-direction (16 threads * TJ=4 -> 64 j)
    const int ty = tid >> 4;   // i-direction (16 threads * TI=4 -> 64 i)
    const int i0 = blockIdx.x * BI;
    const int j0 = blockIdx.y * BJ;

    if (tid < BJ) sW[tid] = W[j0 + tid];

    float acc[TI][TJ];
#pragma unroll
    for (int a = 0; a < TI; a++)
#pragma unroll
        for (int b = 0; b < TJ; b++) acc[a][b] = 1.0f;

    for (int fc = 0; fc < FF; fc += KC) {
        __syncthreads();  // protect previous chunk (and sW on first pass)
        // Fill: KC*64 = 2048 elements per array, 256 threads -> 8 rounds.
        // Consecutive tid -> consecutive row: coalesced gmem, conflict-free smem.
#pragma unroll
        for (int r = 0; r < (KC * BI) / 256; r++) {
            int l = r * 256 + tid;
            int f = l >> 6;
            int row = l & 63;
            sCX[f][row] = g_cX[(fc + f) * BB + i0 + row];
            sSX[f][row] = g_sX[(fc + f) * BB + i0 + row];
            sCS[f][row] = g_cS[(fc + f) * SS + j0 + row];
            sSS[f][row] = g_sS[(fc + f) * SS + j0 + row];
        }
        __syncthreads();

#pragma unroll 4
        for (int f = 0; f < KC; f++) {
            float4 cx4 = *(const float4*)&sCX[f][ty * TI];
            float4 sx4 = *(const float4*)&sSX[f][ty * TI];
            float4 cj4 = *(const float4*)&sCS[f][tx * TJ];
            float4 sj4 = *(const float4*)&sSS[f][tx * TJ];
            float cxv[TI] = {cx4.x, cx4.y, cx4.z, cx4.w};
            float sxv[TI] = {sx4.x, sx4.y, sx4.z, sx4.w};
            float cjv[TJ] = {cj4.x, cj4.y, cj4.z, cj4.w};
            float sjv[TJ] = {sj4.x, sj4.y, sj4.z, sj4.w};
#pragma unroll
            for (int a = 0; a < TI; a++) {
#pragma unroll
                for (int b = 0; b < TJ; b++) {
                    // t = cos((x_a - s_b)/2); accumulate product (square at end)
                    float t = fmaf(cxv[a], cjv[b], sxv[a] * sjv[b]);
                    acc[a][b] *= t;
                }
            }
        }
    }

    // Per-row weighted sum over this thread's 4 j's, then reduce over tx.
#pragma unroll
    for (int a = 0; a < TI; a++) {
        float p = 0.0f;
#pragma unroll
        for (int b = 0; b < TJ; b++) {
            float k = acc[a][b] * acc[a][b];  // K = (prod t)^2
            p = fmaf(k, sW[tx * TJ + b], p);
        }
#pragma unroll
        for (int off = 8; off > 0; off >>= 1)
            p += __shfl_down_sync(0xffffffffu, p, off, 16);
        if (tx == 0) atomicAdd(&out[i0 + ty * TI + a], p);
    }
}

extern "C" void kernel_launch(void* const* d_in, const int* in_sizes, int n_in,
                              void* d_out, int out_size) {
    const float* X  = (const float*)d_in[0];  // [2048, 64]
    const float* Sp = (const float*)d_in[1];  // [1024, 64]
    const float* W  = (const float*)d_in[2];  // [1, 1024]
    const float* b  = (const float*)d_in[3];  // [1]
    float* out = (float*)d_out;               // [2048]

    int total = FF * (BB + SS);
    precomp_kernel<<<(total + 255) / 256, 256>>>(X, Sp);
    init_kernel<<<(BB + 255) / 256, 256>>>(out, b);

    dim3 grid(BB / BI, SS / BJ);  // 32 x 16 = 512 CTAs
    main_kernel<<<grid, 256>>>(W, out);
}